// round 2
// baseline (speedup 1.0000x reference)
#include <cuda_runtime.h>
#include <math.h>

// Problem constants
#define Bb 4
#define Ss 2048
#define Dd 1024
#define Hh 4096
#define MM (Bb * Ss)   // 8192 rows (b,s flattened)

// Scratch (device globals — allocation-free rule)
__device__ float g_h[(size_t)MM * Hh];   // post-GELU hidden, 134 MB
__device__ float g_U1[MM * 4];           // rank-4 lora-1 coefficients
__device__ float g_V[MM * 16];           // rank-16 lora-2 coefficients

__device__ __forceinline__ float gelu_exact(float v) {
    return 0.5f * v * (1.0f + erff(v * 0.70710678118654752f));
}

// packed fp32x2 FMA: d = a*b + d (lanewise on 2 floats in a 64-bit reg)
__device__ __forceinline__ void ffma2(unsigned long long& d,
                                      unsigned long long a,
                                      unsigned long long b) {
    asm("fma.rn.f32x2 %0, %1, %2, %0;" : "+l"(d) : "l"(a), "l"(b));
}

// ---------------------------------------------------------------------------
// U1[b,s,r] = x[b,s,:] . x[b, 2+2r, :]   (odd1 tokens 2,4,6,8); 1 warp/(b,s)
// ---------------------------------------------------------------------------
__global__ void u1_kernel(const float* __restrict__ x) {
    int gw = (blockIdx.x * blockDim.x + threadIdx.x) >> 5;
    int lane = threadIdx.x & 31;
    if (gw >= MM) return;
    int b = gw >> 11;
    const float4* xr = (const float4*)(x + (size_t)gw * Dd);
    const float4* o0 = (const float4*)(x + ((size_t)b * Ss + 2) * Dd);
    const float4* o1 = (const float4*)(x + ((size_t)b * Ss + 4) * Dd);
    const float4* o2 = (const float4*)(x + ((size_t)b * Ss + 6) * Dd);
    const float4* o3 = (const float4*)(x + ((size_t)b * Ss + 8) * Dd);
    float a0 = 0.f, a1 = 0.f, a2 = 0.f, a3 = 0.f;
    for (int j = lane; j < Dd / 4; j += 32) {
        float4 xv = xr[j];
        float4 v;
        v = o0[j]; a0 += xv.x * v.x + xv.y * v.y + xv.z * v.z + xv.w * v.w;
        v = o1[j]; a1 += xv.x * v.x + xv.y * v.y + xv.z * v.z + xv.w * v.w;
        v = o2[j]; a2 += xv.x * v.x + xv.y * v.y + xv.z * v.z + xv.w * v.w;
        v = o3[j]; a3 += xv.x * v.x + xv.y * v.y + xv.z * v.z + xv.w * v.w;
    }
    #pragma unroll
    for (int off = 16; off; off >>= 1) {
        a0 += __shfl_xor_sync(0xFFFFFFFFu, a0, off);
        a1 += __shfl_xor_sync(0xFFFFFFFFu, a1, off);
        a2 += __shfl_xor_sync(0xFFFFFFFFu, a2, off);
        a3 += __shfl_xor_sync(0xFFFFFFFFu, a3, off);
    }
    if (lane == 0) {
        g_U1[gw * 4 + 0] = a0;
        g_U1[gw * 4 + 1] = a1;
        g_U1[gw * 4 + 2] = a2;
        g_U1[gw * 4 + 3] = a3;
    }
}

// ---------------------------------------------------------------------------
// V[b,s,r,k] = sum_j h[b,s, k*1024+j] * x[b, 10+2r, j]; 1 warp/(b,s)
// ---------------------------------------------------------------------------
__global__ void v_kernel(const float* __restrict__ x) {
    int gw = (blockIdx.x * blockDim.x + threadIdx.x) >> 5;
    int lane = threadIdx.x & 31;
    if (gw >= MM) return;
    int b = gw >> 11;
    const float4* od[4];
    #pragma unroll
    for (int r = 0; r < 4; r++)
        od[r] = (const float4*)(x + ((size_t)b * Ss + 10 + 2 * r) * Dd);
    float acc[16];
    #pragma unroll
    for (int i = 0; i < 16; i++) acc[i] = 0.f;
    #pragma unroll
    for (int k = 0; k < 4; k++) {
        const float4* hr = (const float4*)(g_h + (size_t)gw * Hh + k * 1024);
        for (int j = lane; j < 256; j += 32) {
            float4 hv = hr[j];
            #pragma unroll
            for (int r = 0; r < 4; r++) {
                float4 ov = od[r][j];
                acc[r * 4 + k] += hv.x * ov.x + hv.y * ov.y + hv.z * ov.z + hv.w * ov.w;
            }
        }
    }
    #pragma unroll
    for (int i = 0; i < 16; i++) {
        #pragma unroll
        for (int off = 16; off; off >>= 1)
            acc[i] += __shfl_xor_sync(0xFFFFFFFFu, acc[i], off);
    }
    if (lane == 0) {
        #pragma unroll
        for (int i = 0; i < 16; i++) g_V[gw * 16 + i] = acc[i];
    }
}

// ===========================================================================
// FFMA2 GEMM core (shared by gemm1/gemm2 via macro body)
// BM=BN=128, BK=16 (8 k-pairs), 256 threads, 8x8 accum per thread.
// Smem layout k-pair interleaved: As2[buf][kk][m] = (A[2kk][m], A[2kk+1][m]).
// Accumulator lanes = (even-k partial, odd-k partial); summed in epilogue.
// Double-buffered, ONE __syncthreads per K-tile.
// ===========================================================================

#define GEMM_CORE(Aptr, Bptr, Kdim)                                            \
    __shared__ float2 As2[2][8][128];                                          \
    __shared__ float2 Bs2[2][8][128];                                          \
    int tid  = threadIdx.x;                                                    \
    int m0   = blockIdx.y * 128;                                               \
    int n0   = blockIdx.x * 128;                                               \
    int lane = tid & 31, warp = tid >> 5;                                      \
    int wm = warp >> 1, wn = warp & 1;                                         \
    int lm = lane >> 3, ln = lane & 7;                                         \
    int row_a = tid & 127;                                                     \
    int qa    = tid >> 7;                                                      \
    const float4* Ag = (const float4*)((Aptr) + (size_t)(m0 + row_a) * (Kdim));\
    const float4* Bg = (const float4*)((Bptr) + (size_t)(n0 + row_a) * (Kdim));\
    unsigned long long acc[8][8];                                              \
    _Pragma("unroll")                                                          \
    for (int i = 0; i < 8; i++)                                                \
        _Pragma("unroll")                                                      \
        for (int j = 0; j < 8; j++) acc[i][j] = 0ULL;                          \
    float4 pa0 = Ag[qa], pa1 = Ag[qa + 2];                                     \
    float4 pb0 = Bg[qa], pb1 = Bg[qa + 2];                                     \
    const int nk = (Kdim) / 16;                                                \
    int buf = 0;                                                               \
    for (int t = 0; t < nk; ++t) {                                             \
        As2[buf][2 * qa + 0][row_a] = make_float2(pa0.x, pa0.y);               \
        As2[buf][2 * qa + 1][row_a] = make_float2(pa0.z, pa0.w);               \
        As2[buf][2 * qa + 4][row_a] = make_float2(pa1.x, pa1.y);               \
        As2[buf][2 * qa + 5][row_a] = make_float2(pa1.z, pa1.w);               \
        Bs2[buf][2 * qa + 0][row_a] = make_float2(pb0.x, pb0.y);               \
        Bs2[buf][2 * qa + 1][row_a] = make_float2(pb0.z, pb0.w);               \
        Bs2[buf][2 * qa + 4][row_a] = make_float2(pb1.x, pb1.y);               \
        Bs2[buf][2 * qa + 5][row_a] = make_float2(pb1.z, pb1.w);               \
        __syncthreads();                                                       \
        if (t + 1 < nk) {                                                      \
            int kq = (t + 1) * 4;                                              \
            pa0 = Ag[kq + qa]; pa1 = Ag[kq + qa + 2];                          \
            pb0 = Bg[kq + qa]; pb1 = Bg[kq + qa + 2];                          \
        }                                                                      \
        _Pragma("unroll")                                                      \
        for (int kk = 0; kk < 8; ++kk) {                                       \
            const ulonglong2* ap =                                             \
                (const ulonglong2*)&As2[buf][kk][wm * 32 + lm * 8];            \
            const ulonglong2* bp =                                             \
                (const ulonglong2*)&Bs2[buf][kk][wn * 64 + ln * 8];            \
            ulonglong2 av0 = ap[0], av1 = ap[1], av2 = ap[2], av3 = ap[3];     \
            ulonglong2 bv0 = bp[0], bv1 = bp[1], bv2 = bp[2], bv3 = bp[3];     \
            unsigned long long a[8] = {av0.x, av0.y, av1.x, av1.y,             \
                                       av2.x, av2.y, av3.x, av3.y};            \
            unsigned long long bb[8] = {bv0.x, bv0.y, bv1.x, bv1.y,            \
                                        bv2.x, bv2.y, bv3.x, bv3.y};           \
            _Pragma("unroll")                                                  \
            for (int i = 0; i < 8; i++)                                        \
                _Pragma("unroll")                                              \
                for (int j = 0; j < 8; j++)                                    \
                    ffma2(acc[i][j], a[i], bb[j]);                             \
        }                                                                      \
        buf ^= 1;                                                              \
    }

__device__ __forceinline__ float acc_sum(unsigned long long v) {
    float2 p = *reinterpret_cast<float2*>(&v);
    return p.x + p.y;
}

// ---------------------------------------------------------------------------
// GEMM1: h = gelu(x @ W1^T + scale * lora1 + b1);  M=8192, N=4096, K=1024
// ---------------------------------------------------------------------------
__global__ __launch_bounds__(256, 2)
void gemm1_kernel(const float* __restrict__ A,
                  const float* __restrict__ Wt,
                  const float* __restrict__ bias,
                  const float* __restrict__ scale_p)
{
    GEMM_CORE(A, Wt, Dd)

    float sc = *scale_p;
    int col0 = n0 + wn * 64 + ln * 8;
    int r    = col0 >> 10;       // constant across the 8 cols (8-aligned)
    int ci   = col0 & 1023;
    #pragma unroll
    for (int i = 0; i < 8; i++) {
        int m = m0 + wm * 32 + lm * 8 + i;
        int b = m >> 11;
        float u = sc * g_U1[m * 4 + r];
        const float* ev = A + ((size_t)b * Ss + 1 + 2 * r) * Dd + ci;  // even1 token 1+2r
        float* hdst = g_h + (size_t)m * Hh + col0;
        #pragma unroll
        for (int j = 0; j < 8; j++) {
            float c = acc_sum(acc[i][j]) + u * ev[j] + bias[col0 + j];
            hdst[j] = gelu_exact(c);
        }
    }
}

// ---------------------------------------------------------------------------
// GEMM2: out = h @ W2^T + scale * lora2 + b2;  M=8192, N=1024, K=4096
// ---------------------------------------------------------------------------
__global__ __launch_bounds__(256, 2)
void gemm2_kernel(const float* __restrict__ Wt,     // W2: 1024 x 4096
                  const float* __restrict__ bias,
                  const float* __restrict__ x,      // for even2 vectors
                  const float* __restrict__ scale_p,
                  float* __restrict__ out)
{
    GEMM_CORE(g_h, Wt, Hh)

    float sc = *scale_p;
    int col0 = n0 + wn * 64 + ln * 8;
    int r    = col0 >> 8;    // constant across 8 cols
    #pragma unroll
    for (int i = 0; i < 8; i++) {
        int m = m0 + wm * 32 + lm * 8 + i;
        int b = m >> 11;
        float4 vv = *(const float4*)&g_V[m * 16 + r * 4];
        const float4* ev2 = (const float4*)(x + ((size_t)b * Ss + 9 + 2 * r) * Dd); // even2 token 9+2r
        float* od = out + (size_t)m * Dd + col0;
        #pragma unroll
        for (int j = 0; j < 8; j++) {
            int n = col0 + j;
            float4 e = ev2[n & 255];
            float lora = vv.x * e.x + vv.y * e.y + vv.z * e.z + vv.w * e.w;
            od[j] = acc_sum(acc[i][j]) + sc * lora + bias[n];
        }
    }
}

// ---------------------------------------------------------------------------
extern "C" void kernel_launch(void* const* d_in, const int* in_sizes, int n_in,
                              void* d_out, int out_size) {
    const float* x     = (const float*)d_in[0];
    const float* W1    = (const float*)d_in[1];
    const float* b1    = (const float*)d_in[2];
    const float* W2    = (const float*)d_in[3];
    const float* b2    = (const float*)d_in[4];
    const float* scale = (const float*)d_in[5];
    float* out = (float*)d_out;

    u1_kernel<<<MM / 8, 256>>>(x);

    dim3 g1(Hh / 128, MM / 128);   // (32, 64)
    gemm1_kernel<<<g1, 256>>>(x, W1, b1, scale);

    v_kernel<<<MM / 8, 256>>>(x);

    dim3 g2(Dd / 128, MM / 128);   // (8, 64)
    gemm2_kernel<<<g2, 256>>>(W2, b2, x, scale, out);
}

// round 3
// speedup vs baseline: 4.3507x; 4.3507x over previous
#include <cuda_runtime.h>
#include <math.h>

// Problem constants
#define Bb 4
#define Ss 2048
#define Dd 1024
#define Hh 4096
#define MM (Bb * Ss)   // 8192 rows (b,s flattened)

// Scratch (device globals — allocation-free rule)
__device__ float g_h[(size_t)MM * Hh];   // post-GELU hidden, 134 MB
__device__ float g_U1[MM * 4];           // rank-4 lora-1 coefficients
__device__ float g_V[MM * 16];           // rank-16 lora-2 coefficients

__device__ __forceinline__ float gelu_exact(float v) {
    return 0.5f * v * (1.0f + erff(v * 0.70710678118654752f));
}

// packed fp32x2 FMA: d = a*b + d (lanewise on 2 floats in a 64-bit reg)
__device__ __forceinline__ void ffma2(unsigned long long& d,
                                      unsigned long long a,
                                      unsigned long long b) {
    asm("fma.rn.f32x2 %0, %1, %2, %0;" : "+l"(d) : "l"(a), "l"(b));
}

__device__ __forceinline__ float2 unpack2(unsigned long long v) {
    float2 p;
    asm("mov.b64 {%0, %1}, %2;" : "=f"(p.x), "=f"(p.y) : "l"(v));
    return p;
}

// ---------------------------------------------------------------------------
// U1[b,s,r] = x[b,s,:] . x[b, 2+2r, :]   (odd1 tokens 2,4,6,8); 1 warp/(b,s)
// ---------------------------------------------------------------------------
__global__ void u1_kernel(const float* __restrict__ x) {
    int gw = (blockIdx.x * blockDim.x + threadIdx.x) >> 5;
    int lane = threadIdx.x & 31;
    if (gw >= MM) return;
    int b = gw >> 11;
    const float4* xr = (const float4*)(x + (size_t)gw * Dd);
    const float4* o0 = (const float4*)(x + ((size_t)b * Ss + 2) * Dd);
    const float4* o1 = (const float4*)(x + ((size_t)b * Ss + 4) * Dd);
    const float4* o2 = (const float4*)(x + ((size_t)b * Ss + 6) * Dd);
    const float4* o3 = (const float4*)(x + ((size_t)b * Ss + 8) * Dd);
    float a0 = 0.f, a1 = 0.f, a2 = 0.f, a3 = 0.f;
    for (int j = lane; j < Dd / 4; j += 32) {
        float4 xv = xr[j];
        float4 v;
        v = o0[j]; a0 += xv.x * v.x + xv.y * v.y + xv.z * v.z + xv.w * v.w;
        v = o1[j]; a1 += xv.x * v.x + xv.y * v.y + xv.z * v.z + xv.w * v.w;
        v = o2[j]; a2 += xv.x * v.x + xv.y * v.y + xv.z * v.z + xv.w * v.w;
        v = o3[j]; a3 += xv.x * v.x + xv.y * v.y + xv.z * v.z + xv.w * v.w;
    }
    #pragma unroll
    for (int off = 16; off; off >>= 1) {
        a0 += __shfl_xor_sync(0xFFFFFFFFu, a0, off);
        a1 += __shfl_xor_sync(0xFFFFFFFFu, a1, off);
        a2 += __shfl_xor_sync(0xFFFFFFFFu, a2, off);
        a3 += __shfl_xor_sync(0xFFFFFFFFu, a3, off);
    }
    if (lane == 0) {
        g_U1[gw * 4 + 0] = a0;
        g_U1[gw * 4 + 1] = a1;
        g_U1[gw * 4 + 2] = a2;
        g_U1[gw * 4 + 3] = a3;
    }
}

// ---------------------------------------------------------------------------
// V[b,s,r,k] = sum_j h[b,s, k*1024+j] * x[b, 10+2r, j]; 1 warp/(b,s)
// ---------------------------------------------------------------------------
__global__ void v_kernel(const float* __restrict__ x) {
    int gw = (blockIdx.x * blockDim.x + threadIdx.x) >> 5;
    int lane = threadIdx.x & 31;
    if (gw >= MM) return;
    int b = gw >> 11;
    const float4* od[4];
    #pragma unroll
    for (int r = 0; r < 4; r++)
        od[r] = (const float4*)(x + ((size_t)b * Ss + 10 + 2 * r) * Dd);
    float acc[16];
    #pragma unroll
    for (int i = 0; i < 16; i++) acc[i] = 0.f;
    #pragma unroll
    for (int k = 0; k < 4; k++) {
        const float4* hr = (const float4*)(g_h + (size_t)gw * Hh + k * 1024);
        for (int j = lane; j < 256; j += 32) {
            float4 hv = hr[j];
            #pragma unroll
            for (int r = 0; r < 4; r++) {
                float4 ov = od[r][j];
                acc[r * 4 + k] += hv.x * ov.x + hv.y * ov.y + hv.z * ov.z + hv.w * ov.w;
            }
        }
    }
    #pragma unroll
    for (int i = 0; i < 16; i++) {
        #pragma unroll
        for (int off = 16; off; off >>= 1)
            acc[i] += __shfl_xor_sync(0xFFFFFFFFu, acc[i], off);
    }
    if (lane == 0) {
        #pragma unroll
        for (int i = 0; i < 16; i++) g_V[gw * 16 + i] = acc[i];
    }
}

// ===========================================================================
// FFMA2 GEMM core, N-paired accumulators (acc regs UNCHANGED vs scalar: 64).
// BM=BN=128, BK=16, 256 threads, 8(M)x8(N) outputs per thread as 8x4 f32x2.
// A smem stored DUPLICATED: As2[k][m] = (A[m][k], A[m][k])  -> a operand is a
//   natural 64-bit LDS, no per-FFMA packing MOV.
// B smem natural n-pairs: Bs2[k][np] = (B[2np][k], B[2np+1][k]).
// Double-buffered, ONE __syncthreads per K-tile.
// ===========================================================================

#define GEMM_CORE(Aptr, Bptr, Kdim)                                            \
    __shared__ float2 As2[2][16][128];   /* 32 KB */                           \
    __shared__ float2 Bs2[2][16][64];    /* 16 KB */                           \
    int tid  = threadIdx.x;                                                    \
    int m0   = blockIdx.y * 128;                                               \
    int n0   = blockIdx.x * 128;                                               \
    int lane = tid & 31, warp = tid >> 5;                                      \
    int wm = warp >> 1, wn = warp & 1;                                         \
    int lm = lane >> 3, ln = lane & 7;                                         \
    int row_a = tid & 127;                                                     \
    int qa    = tid >> 7;                                                      \
    const float4* Ag = (const float4*)((Aptr) + (size_t)(m0 + row_a) * (Kdim));\
    const float4* Bg = (const float4*)((Bptr) + (size_t)(n0 + row_a) * (Kdim));\
    unsigned long long acc[8][4];                                              \
    _Pragma("unroll")                                                          \
    for (int i = 0; i < 8; i++)                                                \
        _Pragma("unroll")                                                      \
        for (int j = 0; j < 4; j++) acc[i][j] = 0ULL;                          \
    float4 pa0 = Ag[qa], pa1 = Ag[qa + 2];                                     \
    float4 pb0 = Bg[qa], pb1 = Bg[qa + 2];                                     \
    const int nk = (Kdim) / 16;                                                \
    int buf = 0;                                                               \
    for (int t = 0; t < nk; ++t) {                                             \
        /* A duplicated: k rows qa*4..+3 and qa*4+8..+3 */                     \
        As2[buf][qa * 4 + 0][row_a] = make_float2(pa0.x, pa0.x);               \
        As2[buf][qa * 4 + 1][row_a] = make_float2(pa0.y, pa0.y);               \
        As2[buf][qa * 4 + 2][row_a] = make_float2(pa0.z, pa0.z);               \
        As2[buf][qa * 4 + 3][row_a] = make_float2(pa0.w, pa0.w);               \
        As2[buf][qa * 4 + 8][row_a] = make_float2(pa1.x, pa1.x);               \
        As2[buf][qa * 4 + 9][row_a] = make_float2(pa1.y, pa1.y);               \
        As2[buf][qa * 4 + 10][row_a] = make_float2(pa1.z, pa1.z);              \
        As2[buf][qa * 4 + 11][row_a] = make_float2(pa1.w, pa1.w);              \
        /* B scalar halves: float index row_a within the 64-pair row */        \
        ((float*)Bs2[buf][qa * 4 + 0])[row_a] = pb0.x;                         \
        ((float*)Bs2[buf][qa * 4 + 1])[row_a] = pb0.y;                         \
        ((float*)Bs2[buf][qa * 4 + 2])[row_a] = pb0.z;                         \
        ((float*)Bs2[buf][qa * 4 + 3])[row_a] = pb0.w;                         \
        ((float*)Bs2[buf][qa * 4 + 8])[row_a] = pb1.x;                         \
        ((float*)Bs2[buf][qa * 4 + 9])[row_a] = pb1.y;                         \
        ((float*)Bs2[buf][qa * 4 + 10])[row_a] = pb1.z;                        \
        ((float*)Bs2[buf][qa * 4 + 11])[row_a] = pb1.w;                        \
        __syncthreads();                                                       \
        if (t + 1 < nk) {                                                      \
            int kq = (t + 1) * 4;                                              \
            pa0 = Ag[kq + qa]; pa1 = Ag[kq + qa + 2];                          \
            pb0 = Bg[kq + qa]; pb1 = Bg[kq + qa + 2];                          \
        }                                                                      \
        _Pragma("unroll")                                                      \
        for (int kk = 0; kk < 16; ++kk) {                                      \
            const ulonglong2* ap =                                             \
                (const ulonglong2*)&As2[buf][kk][wm * 32 + lm * 8];            \
            const ulonglong2* bp =                                             \
                (const ulonglong2*)&Bs2[buf][kk][wn * 32 + ln * 4];            \
            ulonglong2 av0 = ap[0], av1 = ap[1], av2 = ap[2], av3 = ap[3];     \
            ulonglong2 bv0 = bp[0], bv1 = bp[1];                               \
            unsigned long long a[8] = {av0.x, av0.y, av1.x, av1.y,             \
                                       av2.x, av2.y, av3.x, av3.y};            \
            unsigned long long bb[4] = {bv0.x, bv0.y, bv1.x, bv1.y};           \
            _Pragma("unroll")                                                  \
            for (int i = 0; i < 8; i++)                                        \
                _Pragma("unroll")                                              \
                for (int j = 0; j < 4; j++)                                    \
                    ffma2(acc[i][j], a[i], bb[j]);                             \
        }                                                                      \
        buf ^= 1;                                                              \
    }

// ---------------------------------------------------------------------------
// GEMM1: h = gelu(x @ W1^T + scale * lora1 + b1);  M=8192, N=4096, K=1024
// ---------------------------------------------------------------------------
__global__ __launch_bounds__(256, 2)
void gemm1_kernel(const float* __restrict__ A,
                  const float* __restrict__ Wt,
                  const float* __restrict__ bias,
                  const float* __restrict__ scale_p)
{
    GEMM_CORE(A, Wt, Dd)

    float sc = *scale_p;
    int col0 = n0 + wn * 64 + ln * 8;
    int r    = col0 >> 10;       // constant across the 8 cols (8-aligned)
    int ci   = col0 & 1023;
    #pragma unroll
    for (int i = 0; i < 8; i++) {
        int m = m0 + wm * 32 + lm * 8 + i;
        int b = m >> 11;
        float u = sc * g_U1[m * 4 + r];
        const float* ev = A + ((size_t)b * Ss + 1 + 2 * r) * Dd + ci;  // even1 token 1+2r
        float* hdst = g_h + (size_t)m * Hh + col0;
        #pragma unroll
        for (int j = 0; j < 4; j++) {
            float2 p = unpack2(acc[i][j]);
            float c0 = p.x + u * ev[2 * j]     + bias[col0 + 2 * j];
            float c1 = p.y + u * ev[2 * j + 1] + bias[col0 + 2 * j + 1];
            hdst[2 * j]     = gelu_exact(c0);
            hdst[2 * j + 1] = gelu_exact(c1);
        }
    }
}

// ---------------------------------------------------------------------------
// GEMM2: out = h @ W2^T + scale * lora2 + b2;  M=8192, N=1024, K=4096
// ---------------------------------------------------------------------------
__global__ __launch_bounds__(256, 2)
void gemm2_kernel(const float* __restrict__ Wt,     // W2: 1024 x 4096
                  const float* __restrict__ bias,
                  const float* __restrict__ x,      // for even2 vectors
                  const float* __restrict__ scale_p,
                  float* __restrict__ out)
{
    GEMM_CORE(g_h, Wt, Hh)

    float sc = *scale_p;
    int col0 = n0 + wn * 64 + ln * 8;
    int r    = col0 >> 8;    // constant across 8 cols
    #pragma unroll
    for (int i = 0; i < 8; i++) {
        int m = m0 + wm * 32 + lm * 8 + i;
        int b = m >> 11;
        float4 vv = *(const float4*)&g_V[m * 16 + r * 4];
        const float4* ev2 = (const float4*)(x + ((size_t)b * Ss + 9 + 2 * r) * Dd); // even2 token 9+2r
        float* od = out + (size_t)m * Dd + col0;
        #pragma unroll
        for (int j = 0; j < 4; j++) {
            float2 p = unpack2(acc[i][j]);
            #pragma unroll
            for (int h = 0; h < 2; h++) {
                int n = col0 + 2 * j + h;
                float4 e = ev2[n & 255];
                float lora = vv.x * e.x + vv.y * e.y + vv.z * e.z + vv.w * e.w;
                od[2 * j + h] = (h ? p.y : p.x) + sc * lora + bias[n];
            }
        }
    }
}

// ---------------------------------------------------------------------------
extern "C" void kernel_launch(void* const* d_in, const int* in_sizes, int n_in,
                              void* d_out, int out_size) {
    const float* x     = (const float*)d_in[0];
    const float* W1    = (const float*)d_in[1];
    const float* b1    = (const float*)d_in[2];
    const float* W2    = (const float*)d_in[3];
    const float* b2    = (const float*)d_in[4];
    const float* scale = (const float*)d_in[5];
    float* out = (float*)d_out;

    u1_kernel<<<MM / 8, 256>>>(x);

    dim3 g1(Hh / 128, MM / 128);   // (32, 64)
    gemm1_kernel<<<g1, 256>>>(x, W1, b1, scale);

    v_kernel<<<MM / 8, 256>>>(x);

    dim3 g2(Dd / 128, MM / 128);   // (8, 64)
    gemm2_kernel<<<g2, 256>>>(W2, b2, x, scale, out);
}

// round 5
// speedup vs baseline: 12.6122x; 2.8989x over previous
#include <cuda_runtime.h>
#include <cuda_bf16.h>
#include <math.h>
#include <stdint.h>

// Problem constants
#define Bb 4
#define Ss 2048
#define Dd 1024
#define Hh 4096
#define MM (Bb * Ss)   // 8192

// ---------------------------------------------------------------------------
// Device-global scratch (allocation-free rule)
// ---------------------------------------------------------------------------
__device__ __nv_bfloat16 g_xhi[(size_t)MM * Dd];
__device__ __nv_bfloat16 g_xlo[(size_t)MM * Dd];
__device__ __nv_bfloat16 g_w1hi[(size_t)Hh * Dd];
__device__ __nv_bfloat16 g_w1lo[(size_t)Hh * Dd];
__device__ __nv_bfloat16 g_w2hi[(size_t)Dd * Hh];
__device__ __nv_bfloat16 g_w2lo[(size_t)Dd * Hh];
__device__ __nv_bfloat16 g_hhi[(size_t)MM * Hh];
__device__ __nv_bfloat16 g_hlo[(size_t)MM * Hh];
__device__ float g_U1[MM * 4];
__device__ float g_V[MM * 16];

__device__ __forceinline__ float gelu_exact(float v) {
    return 0.5f * v * (1.0f + erff(v * 0.70710678118654752f));
}

__device__ __forceinline__ uint32_t smem_u32(const void* p) {
    uint32_t a;
    asm("{ .reg .u64 t; cvta.to.shared.u64 t, %1; cvt.u32.u64 %0, t; }"
        : "=r"(a) : "l"(p));
    return a;
}

// ---------------------------------------------------------------------------
// mma / ldmatrix / cp.async primitives (all baseline sm_80+ PTX -> sm_103 OK)
// ---------------------------------------------------------------------------
__device__ __forceinline__ void mma16816(float* d, const uint32_t* a, const uint32_t* b) {
    asm volatile(
        "mma.sync.aligned.m16n8k16.row.col.f32.bf16.bf16.f32 "
        "{%0,%1,%2,%3}, {%4,%5,%6,%7}, {%8,%9}, {%0,%1,%2,%3};"
        : "+f"(d[0]), "+f"(d[1]), "+f"(d[2]), "+f"(d[3])
        : "r"(a[0]), "r"(a[1]), "r"(a[2]), "r"(a[3]), "r"(b[0]), "r"(b[1]));
}

__device__ __forceinline__ void ldm4(uint32_t* r, uint32_t addr) {
    asm volatile("ldmatrix.sync.aligned.m8n8.x4.shared.b16 {%0,%1,%2,%3}, [%4];"
                 : "=r"(r[0]), "=r"(r[1]), "=r"(r[2]), "=r"(r[3]) : "r"(addr));
}

__device__ __forceinline__ void cp16(uint32_t s, const void* g) {
    asm volatile("cp.async.cg.shared.global [%0], [%1], 16;" :: "r"(s), "l"(g));
}
__device__ __forceinline__ void cp_commit() {
    asm volatile("cp.async.commit_group;" ::: "memory");
}
__device__ __forceinline__ void cp_wait0() {
    asm volatile("cp.async.wait_group 0;" ::: "memory");
}
__device__ __forceinline__ void cp_wait1() {
    asm volatile("cp.async.wait_group 1;" ::: "memory");
}

// ---------------------------------------------------------------------------
// Tiling constants
// ---------------------------------------------------------------------------
#define BK 32
#define TSTRIDE 80                    // 32 bf16 = 64B data + 16B pad
#define TILE_B (128 * TSTRIDE)        // 10240 B per tile
#define BUF_B (4 * TILE_B)            // Ahi, Alo, Bhi, Blo
#define SMEM_TOTAL (2 * BUF_B)        // 81920 B double-buffered

extern __shared__ char dsmem[];

// Issue cp.async loads for one BK-chunk into one buffer.
__device__ __forceinline__ void issue_chunk(
    uint32_t sbuf,
    const __nv_bfloat16* __restrict__ Ahi, const __nv_bfloat16* __restrict__ Alo,
    const __nv_bfloat16* __restrict__ Bhi, const __nv_bfloat16* __restrict__ Blo,
    int m0, int n0, int kc, int KDIM, int tid)
{
    #pragma unroll
    for (int i = 0; i < 2; i++) {
        int idx = tid + i * 256;
        int row = idx >> 2, c4 = idx & 3;
        uint32_t soff = (uint32_t)(row * TSTRIDE + c4 * 16);
        size_t ga = (size_t)(m0 + row) * KDIM + kc * BK + c4 * 8;
        size_t gb = (size_t)(n0 + row) * KDIM + kc * BK + c4 * 8;
        cp16(sbuf + 0 * TILE_B + soff, Ahi + ga);
        cp16(sbuf + 1 * TILE_B + soff, Alo + ga);
        cp16(sbuf + 2 * TILE_B + soff, Bhi + gb);
        cp16(sbuf + 3 * TILE_B + soff, Blo + gb);
    }
}

// Load 4 A fragments (64 rows x k16) from a tile.
__device__ __forceinline__ void lda(uint32_t a[4][4], uint32_t tile, int wm, int lane, int ks) {
    uint32_t koff = (uint32_t)(ks * 32 + (lane >> 4) * 16);
    #pragma unroll
    for (int mi = 0; mi < 4; mi++) {
        uint32_t addr = tile + (uint32_t)((wm * 64 + mi * 16 + (lane & 15)) * TSTRIDE) + koff;
        ldm4(a[mi], addr);
    }
}

// Load 4 B fragments (32 cols x k16) from a tile.
__device__ __forceinline__ void ldb(uint32_t b[4][2], uint32_t tile, int wn, int lane, int ks) {
    #pragma unroll
    for (int g = 0; g < 2; g++) {
        int nrow = wn * 32 + g * 16 + (lane & 7) + ((lane >> 4) & 1) * 8;
        uint32_t addr = tile + (uint32_t)(nrow * TSTRIDE) +
                        (uint32_t)(ks * 32 + ((lane >> 3) & 1) * 16);
        uint32_t r[4];
        ldm4(r, addr);
        b[2 * g][0] = r[0]; b[2 * g][1] = r[1];
        b[2 * g + 1][0] = r[2]; b[2 * g + 1][1] = r[3];
    }
}

__device__ __forceinline__ void mma_set(float acc[4][4][4], uint32_t a[4][4], uint32_t b[4][2]) {
    #pragma unroll
    for (int mi = 0; mi < 4; mi++)
        #pragma unroll
        for (int ni = 0; ni < 4; ni++)
            mma16816(acc[mi][ni], a[mi], b[ni]);
}

// Split-bf16 3-term compute on one buffered BK-chunk.
__device__ __forceinline__ void compute_chunk(uint32_t sbuf, int wm, int wn, int lane,
                                              float acc[4][4][4]) {
    #pragma unroll
    for (int ks = 0; ks < 2; ks++) {
        uint32_t a[4][4], b[4][2];
        lda(a, sbuf + 0 * TILE_B, wm, lane, ks);   // Ahi
        ldb(b, sbuf + 2 * TILE_B, wn, lane, ks);   // Bhi
        mma_set(acc, a, b);                        // Ahi * Bhi
        lda(a, sbuf + 1 * TILE_B, wm, lane, ks);   // Alo
        mma_set(acc, a, b);                        // Alo * Bhi
        ldb(b, sbuf + 3 * TILE_B, wn, lane, ks);   // Blo
        lda(a, sbuf + 0 * TILE_B, wm, lane, ks);   // Ahi (reload, saves regs)
        mma_set(acc, a, b);                        // Ahi * Blo
    }
}

// Full mainloop: fills acc for this CTA/warp.
template <int KDIM>
__device__ __forceinline__ void gemm_mma(
    const __nv_bfloat16* __restrict__ Ahi, const __nv_bfloat16* __restrict__ Alo,
    const __nv_bfloat16* __restrict__ Bhi, const __nv_bfloat16* __restrict__ Blo,
    int m0, int n0, float acc[4][4][4])
{
    int tid = threadIdx.x;
    int lane = tid & 31, wid = tid >> 5;
    int wm = wid >> 2, wn = wid & 3;
    uint32_t sbase = smem_u32(dsmem);

    #pragma unroll
    for (int mi = 0; mi < 4; mi++)
        #pragma unroll
        for (int ni = 0; ni < 4; ni++)
            #pragma unroll
            for (int q = 0; q < 4; q++) acc[mi][ni][q] = 0.f;

    const int NC = KDIM / BK;
    issue_chunk(sbase, Ahi, Alo, Bhi, Blo, m0, n0, 0, KDIM, tid);
    cp_commit();
    for (int c = 0; c < NC; c++) {
        if (c + 1 < NC) {
            issue_chunk(sbase + ((c + 1) & 1) * BUF_B, Ahi, Alo, Bhi, Blo,
                        m0, n0, c + 1, KDIM, tid);
            cp_commit();
            cp_wait1();
        } else {
            cp_wait0();
        }
        __syncthreads();
        compute_chunk(sbase + (c & 1) * BUF_B, wm, wn, lane, acc);
        __syncthreads();
    }
}

// ---------------------------------------------------------------------------
// cvt: fp32 -> (hi, lo) bf16 split
// ---------------------------------------------------------------------------
__global__ void cvt_kernel(const float* __restrict__ src,
                           __nv_bfloat16* __restrict__ hi,
                           __nv_bfloat16* __restrict__ lo, int n4) {
    int i = blockIdx.x * blockDim.x + threadIdx.x;
    if (i >= n4) return;
    float4 v = ((const float4*)src)[i];
    __nv_bfloat16 h0 = __float2bfloat16(v.x), h1 = __float2bfloat16(v.y);
    __nv_bfloat16 h2 = __float2bfloat16(v.z), h3 = __float2bfloat16(v.w);
    __nv_bfloat16 l0 = __float2bfloat16(v.x - __bfloat162float(h0));
    __nv_bfloat16 l1 = __float2bfloat16(v.y - __bfloat162float(h1));
    __nv_bfloat16 l2 = __float2bfloat16(v.z - __bfloat162float(h2));
    __nv_bfloat16 l3 = __float2bfloat16(v.w - __bfloat162float(h3));
    ((__nv_bfloat162*)hi)[2 * i]     = __halves2bfloat162(h0, h1);
    ((__nv_bfloat162*)hi)[2 * i + 1] = __halves2bfloat162(h2, h3);
    ((__nv_bfloat162*)lo)[2 * i]     = __halves2bfloat162(l0, l1);
    ((__nv_bfloat162*)lo)[2 * i + 1] = __halves2bfloat162(l2, l3);
}

// ---------------------------------------------------------------------------
// U1[b,s,r] = x[b,s,:] . x[b, 2+2r, :]  (fp32 exact); 1 warp/(b,s)
// ---------------------------------------------------------------------------
__global__ void u1_kernel(const float* __restrict__ x) {
    int gw = (blockIdx.x * blockDim.x + threadIdx.x) >> 5;
    int lane = threadIdx.x & 31;
    if (gw >= MM) return;
    int b = gw >> 11;
    const float4* xr = (const float4*)(x + (size_t)gw * Dd);
    const float4* o0 = (const float4*)(x + ((size_t)b * Ss + 2) * Dd);
    const float4* o1 = (const float4*)(x + ((size_t)b * Ss + 4) * Dd);
    const float4* o2 = (const float4*)(x + ((size_t)b * Ss + 6) * Dd);
    const float4* o3 = (const float4*)(x + ((size_t)b * Ss + 8) * Dd);
    float a0 = 0.f, a1 = 0.f, a2 = 0.f, a3 = 0.f;
    for (int j = lane; j < Dd / 4; j += 32) {
        float4 xv = xr[j];
        float4 v;
        v = o0[j]; a0 += xv.x * v.x + xv.y * v.y + xv.z * v.z + xv.w * v.w;
        v = o1[j]; a1 += xv.x * v.x + xv.y * v.y + xv.z * v.z + xv.w * v.w;
        v = o2[j]; a2 += xv.x * v.x + xv.y * v.y + xv.z * v.z + xv.w * v.w;
        v = o3[j]; a3 += xv.x * v.x + xv.y * v.y + xv.z * v.z + xv.w * v.w;
    }
    #pragma unroll
    for (int off = 16; off; off >>= 1) {
        a0 += __shfl_xor_sync(0xFFFFFFFFu, a0, off);
        a1 += __shfl_xor_sync(0xFFFFFFFFu, a1, off);
        a2 += __shfl_xor_sync(0xFFFFFFFFu, a2, off);
        a3 += __shfl_xor_sync(0xFFFFFFFFu, a3, off);
    }
    if (lane == 0) {
        g_U1[gw * 4 + 0] = a0;
        g_U1[gw * 4 + 1] = a1;
        g_U1[gw * 4 + 2] = a2;
        g_U1[gw * 4 + 3] = a3;
    }
}

// ---------------------------------------------------------------------------
// V[b,s,r,k] = sum_j h[b,s,k*1024+j] * x[b,10+2r,j]; h = hhi + hlo
// ---------------------------------------------------------------------------
__global__ void v_kernel(const float* __restrict__ x) {
    int gw = (blockIdx.x * blockDim.x + threadIdx.x) >> 5;
    int lane = threadIdx.x & 31;
    if (gw >= MM) return;
    int b = gw >> 11;
    const float2* od[4];
    #pragma unroll
    for (int r = 0; r < 4; r++)
        od[r] = (const float2*)(x + ((size_t)b * Ss + 10 + 2 * r) * Dd);
    float acc[16];
    #pragma unroll
    for (int i = 0; i < 16; i++) acc[i] = 0.f;
    #pragma unroll
    for (int k = 0; k < 4; k++) {
        const __nv_bfloat162* hh = (const __nv_bfloat162*)(g_hhi + (size_t)gw * Hh + k * 1024);
        const __nv_bfloat162* hl = (const __nv_bfloat162*)(g_hlo + (size_t)gw * Hh + k * 1024);
        for (int j = lane; j < 512; j += 32) {
            float2 a = __bfloat1622float2(hh[j]);
            float2 c = __bfloat1622float2(hl[j]);
            float hx = a.x + c.x, hy = a.y + c.y;
            #pragma unroll
            for (int r = 0; r < 4; r++) {
                float2 ov = od[r][j];
                acc[r * 4 + k] += hx * ov.x + hy * ov.y;
            }
        }
    }
    #pragma unroll
    for (int i = 0; i < 16; i++) {
        #pragma unroll
        for (int off = 16; off; off >>= 1)
            acc[i] += __shfl_xor_sync(0xFFFFFFFFu, acc[i], off);
    }
    if (lane == 0) {
        #pragma unroll
        for (int i = 0; i < 16; i++) g_V[gw * 16 + i] = acc[i];
    }
}

// ---------------------------------------------------------------------------
// GEMM1: h = gelu(x@W1^T + scale*lora1 + b1) -> split-bf16 g_hhi/g_hlo
// ---------------------------------------------------------------------------
__global__ __launch_bounds__(256)
void gemm1_mma(const float* __restrict__ x, const float* __restrict__ b1,
               const float* __restrict__ scale_p) {
    int m0 = blockIdx.y * 128, n0 = blockIdx.x * 128;
    float acc[4][4][4];
    gemm_mma<Dd>(g_xhi, g_xlo, g_w1hi, g_w1lo, m0, n0, acc);

    int lane = threadIdx.x & 31, wid = threadIdx.x >> 5;
    int wm = wid >> 2, wn = wid & 3;
    float sc = *scale_p;
    int r = n0 >> 10;
    #pragma unroll
    for (int mi = 0; mi < 4; mi++) {
        #pragma unroll
        for (int half = 0; half < 2; half++) {
            int m = m0 + wm * 64 + mi * 16 + (lane >> 2) + half * 8;
            int b = m >> 11;
            float u = sc * g_U1[m * 4 + r];
            const float* ev = x + ((size_t)b * Ss + 1 + 2 * r) * Dd;
            #pragma unroll
            for (int ni = 0; ni < 4; ni++) {
                int n = n0 + wn * 32 + ni * 8 + 2 * (lane & 3);
                int nc = n & 1023;
                float c0 = acc[mi][ni][half * 2 + 0] + u * ev[nc]     + b1[n];
                float c1 = acc[mi][ni][half * 2 + 1] + u * ev[nc + 1] + b1[n + 1];
                float gg0 = gelu_exact(c0), gg1 = gelu_exact(c1);
                __nv_bfloat16 h0 = __float2bfloat16(gg0);
                __nv_bfloat16 h1 = __float2bfloat16(gg1);
                __nv_bfloat16 l0 = __float2bfloat16(gg0 - __bfloat162float(h0));
                __nv_bfloat16 l1 = __float2bfloat16(gg1 - __bfloat162float(h1));
                *(__nv_bfloat162*)(g_hhi + (size_t)m * Hh + n) = __halves2bfloat162(h0, h1);
                *(__nv_bfloat162*)(g_hlo + (size_t)m * Hh + n) = __halves2bfloat162(l0, l1);
            }
        }
    }
}

// ---------------------------------------------------------------------------
// GEMM2: out = h@W2^T + scale*lora2 + b2  (fp32 out)
// ---------------------------------------------------------------------------
__global__ __launch_bounds__(256)
void gemm2_mma(const float* __restrict__ x, const float* __restrict__ b2,
               const float* __restrict__ scale_p, float* __restrict__ out) {
    int m0 = blockIdx.y * 128, n0 = blockIdx.x * 128;
    float acc[4][4][4];
    gemm_mma<Hh>(g_hhi, g_hlo, g_w2hi, g_w2lo, m0, n0, acc);

    int lane = threadIdx.x & 31, wid = threadIdx.x >> 5;
    int wm = wid >> 2, wn = wid & 3;
    float sc = *scale_p;
    int r = n0 >> 8;
    #pragma unroll
    for (int mi = 0; mi < 4; mi++) {
        #pragma unroll
        for (int half = 0; half < 2; half++) {
            int m = m0 + wm * 64 + mi * 16 + (lane >> 2) + half * 8;
            int b = m >> 11;
            float4 vv = *(const float4*)&g_V[m * 16 + r * 4];
            const float4* ev2 = (const float4*)(x + ((size_t)b * Ss + 9 + 2 * r) * Dd);
            #pragma unroll
            for (int ni = 0; ni < 4; ni++) {
                int n = n0 + wn * 32 + ni * 8 + 2 * (lane & 3);
                float4 e0 = ev2[n & 255];
                float4 e1 = ev2[(n + 1) & 255];
                float lora0 = vv.x * e0.x + vv.y * e0.y + vv.z * e0.z + vv.w * e0.w;
                float lora1 = vv.x * e1.x + vv.y * e1.y + vv.z * e1.z + vv.w * e1.w;
                float2 o;
                o.x = acc[mi][ni][half * 2 + 0] + sc * lora0 + b2[n];
                o.y = acc[mi][ni][half * 2 + 1] + sc * lora1 + b2[n + 1];
                *(float2*)(out + (size_t)m * Dd + n) = o;
            }
        }
    }
}

// ---------------------------------------------------------------------------
extern "C" void kernel_launch(void* const* d_in, const int* in_sizes, int n_in,
                              void* d_out, int out_size) {
    const float* x     = (const float*)d_in[0];
    const float* W1    = (const float*)d_in[1];
    const float* b1    = (const float*)d_in[2];
    const float* W2    = (const float*)d_in[3];
    const float* b2    = (const float*)d_in[4];
    const float* scale = (const float*)d_in[5];
    float* out = (float*)d_out;

    cudaFuncSetAttribute(gemm1_mma, cudaFuncAttributeMaxDynamicSharedMemorySize, SMEM_TOTAL);
    cudaFuncSetAttribute(gemm2_mma, cudaFuncAttributeMaxDynamicSharedMemorySize, SMEM_TOTAL);

    __nv_bfloat16 *xhi, *xlo, *w1hi, *w1lo, *w2hi, *w2lo;
    cudaGetSymbolAddress((void**)&xhi, g_xhi);
    cudaGetSymbolAddress((void**)&xlo, g_xlo);
    cudaGetSymbolAddress((void**)&w1hi, g_w1hi);
    cudaGetSymbolAddress((void**)&w1lo, g_w1lo);
    cudaGetSymbolAddress((void**)&w2hi, g_w2hi);
    cudaGetSymbolAddress((void**)&w2lo, g_w2lo);

    cvt_kernel<<<(MM * Dd / 4 + 255) / 256, 256>>>(x, xhi, xlo, MM * Dd / 4);
    cvt_kernel<<<(Hh * Dd / 4 + 255) / 256, 256>>>(W1, w1hi, w1lo, Hh * Dd / 4);
    cvt_kernel<<<(Dd * Hh / 4 + 255) / 256, 256>>>(W2, w2hi, w2lo, Dd * Hh / 4);

    u1_kernel<<<MM / 8, 256>>>(x);

    dim3 g1(Hh / 128, MM / 128);   // (32, 64)
    gemm1_mma<<<g1, 256, SMEM_TOTAL>>>(x, b1, scale);

    v_kernel<<<MM / 8, 256>>>(x);

    dim3 g2(Dd / 128, MM / 128);   // (8, 64)
    gemm2_mma<<<g2, 256, SMEM_TOTAL>>>(x, b2, scale, out);
}

// round 6
// speedup vs baseline: 15.1227x; 1.1991x over previous
#include <cuda_runtime.h>
#include <cuda_bf16.h>
#include <math.h>
#include <stdint.h>

// Problem constants
#define Bb 4
#define Ss 2048
#define Dd 1024
#define Hh 4096
#define MM (Bb * Ss)   // 8192

// ---------------------------------------------------------------------------
// Device-global scratch (allocation-free rule)
// ---------------------------------------------------------------------------
__device__ __nv_bfloat16 g_xhi[(size_t)MM * Dd];
__device__ __nv_bfloat16 g_xlo[(size_t)MM * Dd];
__device__ __nv_bfloat16 g_w1hi[(size_t)Hh * Dd];
__device__ __nv_bfloat16 g_w1lo[(size_t)Hh * Dd];
__device__ __nv_bfloat16 g_w2hi[(size_t)Dd * Hh];
__device__ __nv_bfloat16 g_w2lo[(size_t)Dd * Hh];
__device__ __nv_bfloat16 g_hhi[(size_t)MM * Hh];
__device__ __nv_bfloat16 g_hlo[(size_t)MM * Hh];
__device__ float g_U1[MM * 4];
__device__ float g_V[MM * 16];

__device__ __forceinline__ float gelu_exact(float v) {
    return 0.5f * v * (1.0f + erff(v * 0.70710678118654752f));
}

__device__ __forceinline__ uint32_t smem_u32(const void* p) {
    uint32_t a;
    asm("{ .reg .u64 t; cvta.to.shared.u64 t, %1; cvt.u32.u64 %0, t; }"
        : "=r"(a) : "l"(p));
    return a;
}

// ---------------------------------------------------------------------------
// mma / ldmatrix / cp.async primitives (baseline sm_80+ PTX -> sm_103 OK)
// ---------------------------------------------------------------------------
__device__ __forceinline__ void mma16816(float* d, const uint32_t* a, const uint32_t* b) {
    asm volatile(
        "mma.sync.aligned.m16n8k16.row.col.f32.bf16.bf16.f32 "
        "{%0,%1,%2,%3}, {%4,%5,%6,%7}, {%8,%9}, {%0,%1,%2,%3};"
        : "+f"(d[0]), "+f"(d[1]), "+f"(d[2]), "+f"(d[3])
        : "r"(a[0]), "r"(a[1]), "r"(a[2]), "r"(a[3]), "r"(b[0]), "r"(b[1]));
}

__device__ __forceinline__ void ldm4(uint32_t* r, uint32_t addr) {
    asm volatile("ldmatrix.sync.aligned.m8n8.x4.shared.b16 {%0,%1,%2,%3}, [%4];"
                 : "=r"(r[0]), "=r"(r[1]), "=r"(r[2]), "=r"(r[3]) : "r"(addr));
}

__device__ __forceinline__ void cp16(uint32_t s, const void* g) {
    asm volatile("cp.async.cg.shared.global [%0], [%1], 16;" :: "r"(s), "l"(g));
}
__device__ __forceinline__ void cp_commit() {
    asm volatile("cp.async.commit_group;" ::: "memory");
}
__device__ __forceinline__ void cp_wait0() {
    asm volatile("cp.async.wait_group 0;" ::: "memory");
}
__device__ __forceinline__ void cp_wait1() {
    asm volatile("cp.async.wait_group 1;" ::: "memory");
}

// ---------------------------------------------------------------------------
// Tiling constants
// ---------------------------------------------------------------------------
#define BK 32
#define TSTRIDE 80                    // 32 bf16 = 64B data + 16B pad
#define TILE_B (128 * TSTRIDE)        // 10240 B per tile
#define BUF_B (4 * TILE_B)            // Ahi, Alo, Bhi, Blo
#define SMEM_TOTAL (2 * BUF_B)        // 81920 B double-buffered

extern __shared__ char dsmem[];

// Issue cp.async loads for one BK-chunk into one buffer.
__device__ __forceinline__ void issue_chunk(
    uint32_t sbuf,
    const __nv_bfloat16* __restrict__ Ahi, const __nv_bfloat16* __restrict__ Alo,
    const __nv_bfloat16* __restrict__ Bhi, const __nv_bfloat16* __restrict__ Blo,
    int m0, int n0, int kc, int KDIM, int tid)
{
    #pragma unroll
    for (int i = 0; i < 2; i++) {
        int idx = tid + i * 256;
        int row = idx >> 2, c4 = idx & 3;
        uint32_t soff = (uint32_t)(row * TSTRIDE + c4 * 16);
        size_t ga = (size_t)(m0 + row) * KDIM + kc * BK + c4 * 8;
        size_t gb = (size_t)(n0 + row) * KDIM + kc * BK + c4 * 8;
        cp16(sbuf + 0 * TILE_B + soff, Ahi + ga);
        cp16(sbuf + 1 * TILE_B + soff, Alo + ga);
        cp16(sbuf + 2 * TILE_B + soff, Bhi + gb);
        cp16(sbuf + 3 * TILE_B + soff, Blo + gb);
    }
}

// Load 4 A fragments (64 rows x k16) from a tile.
__device__ __forceinline__ void lda(uint32_t a[4][4], uint32_t tile, int wm, int lane, int ks) {
    uint32_t koff = (uint32_t)(ks * 32 + (lane >> 4) * 16);
    #pragma unroll
    for (int mi = 0; mi < 4; mi++) {
        uint32_t addr = tile + (uint32_t)((wm * 64 + mi * 16 + (lane & 15)) * TSTRIDE) + koff;
        ldm4(a[mi], addr);
    }
}

// Load 4 B fragments (32 cols x k16) from a tile.
__device__ __forceinline__ void ldb(uint32_t b[4][2], uint32_t tile, int wn, int lane, int ks) {
    #pragma unroll
    for (int g = 0; g < 2; g++) {
        int nrow = wn * 32 + g * 16 + (lane & 7) + ((lane >> 4) & 1) * 8;
        uint32_t addr = tile + (uint32_t)(nrow * TSTRIDE) +
                        (uint32_t)(ks * 32 + ((lane >> 3) & 1) * 16);
        uint32_t r[4];
        ldm4(r, addr);
        b[2 * g][0] = r[0]; b[2 * g][1] = r[1];
        b[2 * g + 1][0] = r[2]; b[2 * g + 1][1] = r[3];
    }
}

__device__ __forceinline__ void mma_set(float acc[4][4][4], uint32_t a[4][4], uint32_t b[4][2]) {
    #pragma unroll
    for (int mi = 0; mi < 4; mi++)
        #pragma unroll
        for (int ni = 0; ni < 4; ni++)
            mma16816(acc[mi][ni], a[mi], b[ni]);
}

// Split-bf16 3-term compute on one buffered BK-chunk.
// 12 LDSM + 48 MMA per k16-step (keep both B fragment sets live; A reused once).
__device__ __forceinline__ void compute_chunk(uint32_t sbuf, int wm, int wn, int lane,
                                              float acc[4][4][4]) {
    #pragma unroll
    for (int ks = 0; ks < 2; ks++) {
        uint32_t a[4][4], b_hi[4][2], b_lo[4][2];
        lda(a, sbuf + 0 * TILE_B, wm, lane, ks);   // Ahi
        ldb(b_hi, sbuf + 2 * TILE_B, wn, lane, ks);
        mma_set(acc, a, b_hi);                     // Ahi * Bhi
        ldb(b_lo, sbuf + 3 * TILE_B, wn, lane, ks);
        mma_set(acc, a, b_lo);                     // Ahi * Blo
        lda(a, sbuf + 1 * TILE_B, wm, lane, ks);   // Alo (overwrite)
        mma_set(acc, a, b_hi);                     // Alo * Bhi
    }
}

// Full mainloop: fills acc for this CTA/warp.
template <int KDIM>
__device__ __forceinline__ void gemm_mma(
    const __nv_bfloat16* __restrict__ Ahi, const __nv_bfloat16* __restrict__ Alo,
    const __nv_bfloat16* __restrict__ Bhi, const __nv_bfloat16* __restrict__ Blo,
    int m0, int n0, float acc[4][4][4])
{
    int tid = threadIdx.x;
    int lane = tid & 31, wid = tid >> 5;
    int wm = wid >> 2, wn = wid & 3;
    uint32_t sbase = smem_u32(dsmem);

    #pragma unroll
    for (int mi = 0; mi < 4; mi++)
        #pragma unroll
        for (int ni = 0; ni < 4; ni++)
            #pragma unroll
            for (int q = 0; q < 4; q++) acc[mi][ni][q] = 0.f;

    const int NC = KDIM / BK;
    issue_chunk(sbase, Ahi, Alo, Bhi, Blo, m0, n0, 0, KDIM, tid);
    cp_commit();
    for (int c = 0; c < NC; c++) {
        if (c + 1 < NC) {
            issue_chunk(sbase + ((c + 1) & 1) * BUF_B, Ahi, Alo, Bhi, Blo,
                        m0, n0, c + 1, KDIM, tid);
            cp_commit();
            cp_wait1();
        } else {
            cp_wait0();
        }
        __syncthreads();
        compute_chunk(sbase + (c & 1) * BUF_B, wm, wn, lane, acc);
        __syncthreads();
    }
}

// ---------------------------------------------------------------------------
// cvt: fp32 -> (hi, lo) bf16 split
// ---------------------------------------------------------------------------
__global__ void cvt_kernel(const float* __restrict__ src,
                           __nv_bfloat16* __restrict__ hi,
                           __nv_bfloat16* __restrict__ lo, int n4) {
    int i = blockIdx.x * blockDim.x + threadIdx.x;
    if (i >= n4) return;
    float4 v = ((const float4*)src)[i];
    __nv_bfloat16 h0 = __float2bfloat16(v.x), h1 = __float2bfloat16(v.y);
    __nv_bfloat16 h2 = __float2bfloat16(v.z), h3 = __float2bfloat16(v.w);
    __nv_bfloat16 l0 = __float2bfloat16(v.x - __bfloat162float(h0));
    __nv_bfloat16 l1 = __float2bfloat16(v.y - __bfloat162float(h1));
    __nv_bfloat16 l2 = __float2bfloat16(v.z - __bfloat162float(h2));
    __nv_bfloat16 l3 = __float2bfloat16(v.w - __bfloat162float(h3));
    ((__nv_bfloat162*)hi)[2 * i]     = __halves2bfloat162(h0, h1);
    ((__nv_bfloat162*)hi)[2 * i + 1] = __halves2bfloat162(h2, h3);
    ((__nv_bfloat162*)lo)[2 * i]     = __halves2bfloat162(l0, l1);
    ((__nv_bfloat162*)lo)[2 * i + 1] = __halves2bfloat162(l2, l3);
}

// ---------------------------------------------------------------------------
// U1[b,s,r] = x[b,s,:] . x[b, 2+2r, :]  (fp32 exact); 1 warp/(b,s)
// ---------------------------------------------------------------------------
__global__ void u1_kernel(const float* __restrict__ x) {
    int gw = (blockIdx.x * blockDim.x + threadIdx.x) >> 5;
    int lane = threadIdx.x & 31;
    if (gw >= MM) return;
    int b = gw >> 11;
    const float4* xr = (const float4*)(x + (size_t)gw * Dd);
    const float4* o0 = (const float4*)(x + ((size_t)b * Ss + 2) * Dd);
    const float4* o1 = (const float4*)(x + ((size_t)b * Ss + 4) * Dd);
    const float4* o2 = (const float4*)(x + ((size_t)b * Ss + 6) * Dd);
    const float4* o3 = (const float4*)(x + ((size_t)b * Ss + 8) * Dd);
    float a0 = 0.f, a1 = 0.f, a2 = 0.f, a3 = 0.f;
    for (int j = lane; j < Dd / 4; j += 32) {
        float4 xv = xr[j];
        float4 v;
        v = o0[j]; a0 += xv.x * v.x + xv.y * v.y + xv.z * v.z + xv.w * v.w;
        v = o1[j]; a1 += xv.x * v.x + xv.y * v.y + xv.z * v.z + xv.w * v.w;
        v = o2[j]; a2 += xv.x * v.x + xv.y * v.y + xv.z * v.z + xv.w * v.w;
        v = o3[j]; a3 += xv.x * v.x + xv.y * v.y + xv.z * v.z + xv.w * v.w;
    }
    #pragma unroll
    for (int off = 16; off; off >>= 1) {
        a0 += __shfl_xor_sync(0xFFFFFFFFu, a0, off);
        a1 += __shfl_xor_sync(0xFFFFFFFFu, a1, off);
        a2 += __shfl_xor_sync(0xFFFFFFFFu, a2, off);
        a3 += __shfl_xor_sync(0xFFFFFFFFu, a3, off);
    }
    if (lane == 0) {
        g_U1[gw * 4 + 0] = a0;
        g_U1[gw * 4 + 1] = a1;
        g_U1[gw * 4 + 2] = a2;
        g_U1[gw * 4 + 3] = a3;
    }
}

// ---------------------------------------------------------------------------
// V[b,s,r,k] = sum_j h[b,s,k*1024+j] * x[b,10+2r,j]; h = hhi + hlo
// ---------------------------------------------------------------------------
__global__ void v_kernel(const float* __restrict__ x) {
    int gw = (blockIdx.x * blockDim.x + threadIdx.x) >> 5;
    int lane = threadIdx.x & 31;
    if (gw >= MM) return;
    int b = gw >> 11;
    const float2* od[4];
    #pragma unroll
    for (int r = 0; r < 4; r++)
        od[r] = (const float2*)(x + ((size_t)b * Ss + 10 + 2 * r) * Dd);
    float acc[16];
    #pragma unroll
    for (int i = 0; i < 16; i++) acc[i] = 0.f;
    #pragma unroll
    for (int k = 0; k < 4; k++) {
        const __nv_bfloat162* hh = (const __nv_bfloat162*)(g_hhi + (size_t)gw * Hh + k * 1024);
        const __nv_bfloat162* hl = (const __nv_bfloat162*)(g_hlo + (size_t)gw * Hh + k * 1024);
        for (int j = lane; j < 512; j += 32) {
            float2 a = __bfloat1622float2(hh[j]);
            float2 c = __bfloat1622float2(hl[j]);
            float hx = a.x + c.x, hy = a.y + c.y;
            #pragma unroll
            for (int r = 0; r < 4; r++) {
                float2 ov = od[r][j];
                acc[r * 4 + k] += hx * ov.x + hy * ov.y;
            }
        }
    }
    #pragma unroll
    for (int i = 0; i < 16; i++) {
        #pragma unroll
        for (int off = 16; off; off >>= 1)
            acc[i] += __shfl_xor_sync(0xFFFFFFFFu, acc[i], off);
    }
    if (lane == 0) {
        #pragma unroll
        for (int i = 0; i < 16; i++) g_V[gw * 16 + i] = acc[i];
    }
}

// ---------------------------------------------------------------------------
// GEMM1: h = gelu(x@W1^T + scale*lora1 + b1) -> split-bf16 g_hhi/g_hlo
// ---------------------------------------------------------------------------
__global__ __launch_bounds__(256, 2)
void gemm1_mma(const float* __restrict__ x, const float* __restrict__ b1,
               const float* __restrict__ scale_p) {
    int m0 = blockIdx.y * 128, n0 = blockIdx.x * 128;
    float acc[4][4][4];
    gemm_mma<Dd>(g_xhi, g_xlo, g_w1hi, g_w1lo, m0, n0, acc);

    int lane = threadIdx.x & 31, wid = threadIdx.x >> 5;
    int wm = wid >> 2, wn = wid & 3;
    float sc = *scale_p;
    int r = n0 >> 10;
    #pragma unroll
    for (int mi = 0; mi < 4; mi++) {
        #pragma unroll
        for (int half = 0; half < 2; half++) {
            int m = m0 + wm * 64 + mi * 16 + (lane >> 2) + half * 8;
            int b = m >> 11;
            float u = sc * g_U1[m * 4 + r];
            const float* ev = x + ((size_t)b * Ss + 1 + 2 * r) * Dd;
            #pragma unroll
            for (int ni = 0; ni < 4; ni++) {
                int n = n0 + wn * 32 + ni * 8 + 2 * (lane & 3);
                int nc = n & 1023;
                float c0 = acc[mi][ni][half * 2 + 0] + u * ev[nc]     + b1[n];
                float c1 = acc[mi][ni][half * 2 + 1] + u * ev[nc + 1] + b1[n + 1];
                float gg0 = gelu_exact(c0), gg1 = gelu_exact(c1);
                __nv_bfloat16 h0 = __float2bfloat16(gg0);
                __nv_bfloat16 h1 = __float2bfloat16(gg1);
                __nv_bfloat16 l0 = __float2bfloat16(gg0 - __bfloat162float(h0));
                __nv_bfloat16 l1 = __float2bfloat16(gg1 - __bfloat162float(h1));
                *(__nv_bfloat162*)(g_hhi + (size_t)m * Hh + n) = __halves2bfloat162(h0, h1);
                *(__nv_bfloat162*)(g_hlo + (size_t)m * Hh + n) = __halves2bfloat162(l0, l1);
            }
        }
    }
}

// ---------------------------------------------------------------------------
// GEMM2: out = h@W2^T + scale*lora2 + b2  (fp32 out)
// ---------------------------------------------------------------------------
__global__ __launch_bounds__(256, 2)
void gemm2_mma(const float* __restrict__ x, const float* __restrict__ b2,
               const float* __restrict__ scale_p, float* __restrict__ out) {
    int m0 = blockIdx.y * 128, n0 = blockIdx.x * 128;
    float acc[4][4][4];
    gemm_mma<Hh>(g_hhi, g_hlo, g_w2hi, g_w2lo, m0, n0, acc);

    int lane = threadIdx.x & 31, wid = threadIdx.x >> 5;
    int wm = wid >> 2, wn = wid & 3;
    float sc = *scale_p;
    int r = n0 >> 8;
    #pragma unroll
    for (int mi = 0; mi < 4; mi++) {
        #pragma unroll
        for (int half = 0; half < 2; half++) {
            int m = m0 + wm * 64 + mi * 16 + (lane >> 2) + half * 8;
            int b = m >> 11;
            float4 vv = *(const float4*)&g_V[m * 16 + r * 4];
            const float4* ev2 = (const float4*)(x + ((size_t)b * Ss + 9 + 2 * r) * Dd);
            #pragma unroll
            for (int ni = 0; ni < 4; ni++) {
                int n = n0 + wn * 32 + ni * 8 + 2 * (lane & 3);
                float4 e0 = ev2[n & 255];
                float4 e1 = ev2[(n + 1) & 255];
                float lora0 = vv.x * e0.x + vv.y * e0.y + vv.z * e0.z + vv.w * e0.w;
                float lora1 = vv.x * e1.x + vv.y * e1.y + vv.z * e1.z + vv.w * e1.w;
                float2 o;
                o.x = acc[mi][ni][half * 2 + 0] + sc * lora0 + b2[n];
                o.y = acc[mi][ni][half * 2 + 1] + sc * lora1 + b2[n + 1];
                *(float2*)(out + (size_t)m * Dd + n) = o;
            }
        }
    }
}

// ---------------------------------------------------------------------------
extern "C" void kernel_launch(void* const* d_in, const int* in_sizes, int n_in,
                              void* d_out, int out_size) {
    const float* x     = (const float*)d_in[0];
    const float* W1    = (const float*)d_in[1];
    const float* b1    = (const float*)d_in[2];
    const float* W2    = (const float*)d_in[3];
    const float* b2    = (const float*)d_in[4];
    const float* scale = (const float*)d_in[5];
    float* out = (float*)d_out;

    cudaFuncSetAttribute(gemm1_mma, cudaFuncAttributeMaxDynamicSharedMemorySize, SMEM_TOTAL);
    cudaFuncSetAttribute(gemm2_mma, cudaFuncAttributeMaxDynamicSharedMemorySize, SMEM_TOTAL);

    __nv_bfloat16 *xhi, *xlo, *w1hi, *w1lo, *w2hi, *w2lo;
    cudaGetSymbolAddress((void**)&xhi, g_xhi);
    cudaGetSymbolAddress((void**)&xlo, g_xlo);
    cudaGetSymbolAddress((void**)&w1hi, g_w1hi);
    cudaGetSymbolAddress((void**)&w1lo, g_w1lo);
    cudaGetSymbolAddress((void**)&w2hi, g_w2hi);
    cudaGetSymbolAddress((void**)&w2lo, g_w2lo);

    cvt_kernel<<<(MM * Dd / 4 + 255) / 256, 256>>>(x, xhi, xlo, MM * Dd / 4);
    cvt_kernel<<<(Hh * Dd / 4 + 255) / 256, 256>>>(W1, w1hi, w1lo, Hh * Dd / 4);
    cvt_kernel<<<(Dd * Hh / 4 + 255) / 256, 256>>>(W2, w2hi, w2lo, Dd * Hh / 4);

    u1_kernel<<<MM / 8, 256>>>(x);

    dim3 g1(Hh / 128, MM / 128);   // (32, 64)
    gemm1_mma<<<g1, 256, SMEM_TOTAL>>>(x, b1, scale);

    v_kernel<<<MM / 8, 256>>>(x);

    dim3 g2(Dd / 128, MM / 128);   // (8, 64)
    gemm2_mma<<<g2, 256, SMEM_TOTAL>>>(x, b2, scale, out);
}